// round 5
// baseline (speedup 1.0000x reference)
#include <cuda_runtime.h>
#include <cuda_bf16.h>

// Problem constants (fixed shapes for this bench)
#define B_   16
#define C_   256
#define H_   224
#define W_   224
#define P_   14
#define NH_  16
#define NW_  16
#define N_   256          // NH_*NW_ patches
#define CC_  4            // channels per chunk
#define NCH_ 64           // C_/CC_
#define EPS_COS  1e-8f
#define EPS_NORM 1e-12f

// Scratch (written fully every launch; no init kernel needed)
__device__ float g_dot[NCH_ * B_ * N_];   // [chunk][b][n]  (1 MB)
__device__ float g_nsq[NCH_ * B_ * N_];   // [chunk][b][n]  (1 MB)
__device__ float g_qsq[NCH_ * B_];        // [chunk][b]
__device__ float g_loss[B_];

// ---------------------------------------------------------------------------
// Kernel 1: per (chunk, patch-row, batch) accumulate dot(t,q) and ||t||^2
// Block = 224 threads = 7 full warps, ALL streaming (no idle warp).
// Each thread owns one image column: CC_ channels x 14 rows, coalesced LDG.
// ---------------------------------------------------------------------------
__global__ __launch_bounds__(224)
void accum_kernel(const float* __restrict__ qf,
                  const float* __restrict__ rf,
                  const int*   __restrict__ click) {
    __shared__ float smq[CC_ * P_ * P_];   // 784 floats = 3.06 KB
    __shared__ float sred[2 * 224];        // column partials (dot | nsq)

    const int chunk = blockIdx.x;
    const int ph    = blockIdx.y;
    const int b     = blockIdx.z;
    const int tid   = threadIdx.x;         // 0..223
    const int c0    = chunk * CC_;

    const int qx = click[2 * b + 0];
    const int qy = click[2 * b + 1];
    const int qh = qy / P_;
    const int qw = qx / P_;

    // Stage query patch tile (CC_ channels x 14 x 14) into smem
    const float* qbase = qf + ((size_t)(b * C_ + c0) * H_ + qh * P_) * W_ + qw * P_;
    for (int idx = tid; idx < CC_ * P_ * P_; idx += 224) {
        int cc = idx / (P_ * P_);
        int r  = idx - cc * (P_ * P_);
        int i  = r / P_;
        int j  = r - i * P_;
        smq[idx] = qbase[(cc * H_ + i) * W_ + j];
    }
    __syncthreads();

    // Each thread owns one image column w in [0,224): 128B/warp coalesced loads
    {
        const int w  = tid;
        const int pw = w / P_;
        const int j  = w - pw * P_;
        const float* tbase = rf + ((size_t)(b * C_ + c0) * H_ + ph * P_) * W_ + w;
        float dot = 0.f, nsq = 0.f;
#pragma unroll
        for (int cc = 0; cc < CC_; ++cc) {
            const float* tp = tbase + cc * (H_ * W_);
            const float* qp = smq + cc * (P_ * P_) + j;
#pragma unroll
            for (int i = 0; i < P_; ++i) {
                float t  = __ldcs(tp + i * W_);   // streaming, evict-first
                float qv = qp[i * P_];
                dot = fmaf(t, qv, dot);
                nsq = fmaf(t, t, nsq);
            }
        }
        sred[w]       = dot;
        sred[224 + w] = nsq;
    }
    __syncthreads();

    // Reduce 14 columns -> one patch; write disjoint slots (no atomics)
    if (tid < NW_) {
        float d = 0.f, s = 0.f;
#pragma unroll
        for (int k = 0; k < P_; ++k) {
            d += sred[tid * P_ + k];
            s += sred[224 + tid * P_ + k];
        }
        const int n = ph * NW_ + tid;
        g_dot[(chunk * B_ + b) * N_ + n] = d;
        g_nsq[(chunk * B_ + b) * N_ + n] = s;
    }

    // ph==0 CTAs also compute partial ||q||^2 (warp-shuffle reduction)
    if (ph == 0) {
        float acc = 0.f;
        for (int idx = tid; idx < CC_ * P_ * P_; idx += 224) {
            float v = smq[idx];
            acc = fmaf(v, v, acc);
        }
#pragma unroll
        for (int o = 16; o > 0; o >>= 1)
            acc += __shfl_down_sync(0xffffffffu, acc, o);
        __syncthreads();                   // sred reuse safe (patch writers done)
        if ((tid & 31) == 0) sred[tid >> 5] = acc;   // 7 warp leaders
        __syncthreads();
        if (tid == 0) {
            float t = 0.f;
#pragma unroll
            for (int k = 0; k < 7; ++k) t += sred[k];
            g_qsq[chunk * B_ + b] = t;
        }
    }
}

// ---------------------------------------------------------------------------
// Kernel 2: per-batch cosine-sim -> normalize -> log-softmax -> loss_b
// ---------------------------------------------------------------------------
__global__ __launch_bounds__(256)
void finalizeA_kernel(const float* __restrict__ logit_scale,
                      const int*   __restrict__ gt) {
    const int b   = blockIdx.x;
    const int tid = threadIdx.x;
    __shared__ float sh[256];

    // ||q||^2 = sum of chunk partials
    sh[tid] = (tid < NCH_) ? g_qsq[tid * B_ + b] : 0.f;
    __syncthreads();
    for (int s = 128; s > 0; s >>= 1) {
        if (tid < s) sh[tid] += sh[tid + s];
        __syncthreads();
    }
    const float Qc = fmaxf(sqrtf(sh[0]), EPS_COS);
    __syncthreads();

    // Per-patch (n == tid) sums across chunks
    const int n = tid;
    float dot = 0.f, tsq = 0.f;
#pragma unroll 8
    for (int ch = 0; ch < NCH_; ++ch) {
        dot += g_dot[(ch * B_ + b) * N_ + n];
        tsq += g_nsq[(ch * B_ + b) * N_ + n];
    }
    float s_n = dot / (fmaxf(sqrtf(tsq), EPS_COS) * Qc);

    // F.normalize over the 256-wide sim vector
    sh[tid] = s_n * s_n;
    __syncthreads();
    for (int s = 128; s > 0; s >>= 1) {
        if (tid < s) sh[tid] += sh[tid + s];
        __syncthreads();
    }
    const float r = fmaxf(sqrtf(sh[0]), EPS_NORM);
    __syncthreads();

    const float l = logit_scale[0] * (s_n / r);

    // log-softmax: max
    sh[tid] = l;
    __syncthreads();
    for (int s = 128; s > 0; s >>= 1) {
        if (tid < s) sh[tid] = fmaxf(sh[tid], sh[tid + s]);
        __syncthreads();
    }
    const float m = sh[0];
    __syncthreads();

    // sum exp
    sh[tid] = __expf(l - m);
    __syncthreads();
    for (int s = 128; s > 0; s >>= 1) {
        if (tid < s) sh[tid] += sh[tid + s];
        __syncthreads();
    }
    const float lse = m + logf(sh[0]);

    const int gx = gt[2 * b + 0];
    const int gy = gt[2 * b + 1];
    const int label = (gy / P_) * NW_ + (gx / P_);
    if (n == label) g_loss[b] = lse - l;   // -logp[label]
}

// ---------------------------------------------------------------------------
// Kernel 3: mean over batches
// ---------------------------------------------------------------------------
__global__ void finalizeB_kernel(float* __restrict__ out) {
    if (threadIdx.x == 0) {
        float acc = 0.f;
        for (int b = 0; b < B_; ++b) acc += g_loss[b];
        out[0] = acc / (float)B_;
    }
}

// ---------------------------------------------------------------------------
extern "C" void kernel_launch(void* const* d_in, const int* in_sizes, int n_in,
                              void* d_out, int out_size) {
    const float* qf    = (const float*)d_in[0];   // query_feature [16,256,224,224]
    const float* rf    = (const float*)d_in[1];   // ref_feature   [16,256,224,224]
    const float* scale = (const float*)d_in[2];   // logit_scale scalar
    const int*   click = (const int*)  d_in[3];   // click_points [16,2] int32
    const int*   gt    = (const int*)  d_in[4];   // gt_points    [16,2] int32
    // d_in[5] = patch_size (14), fixed -> hardcoded

    dim3 grid(NCH_, NH_, B_);
    accum_kernel<<<grid, 224>>>(qf, rf, click);
    finalizeA_kernel<<<B_, 256>>>(scale, gt);
    finalizeB_kernel<<<1, 32>>>((float*)d_out);
}

// round 6
// speedup vs baseline: 1.0125x; 1.0125x over previous
#include <cuda_runtime.h>
#include <cuda_bf16.h>

// Problem constants (fixed shapes for this bench)
#define B_   16
#define C_   256
#define H_   224
#define W_   224
#define P_   14
#define NH_  16
#define NW_  16
#define N_   256          // NH_*NW_ patches
#define CC_  4            // channels per tile
#define NCH_ 64           // C_/CC_
#define NTILE_ (NCH_ * B_ * NH_)   // 16384 logical tiles
#define NCTA_  1332                // 148 SMs x 9 resident CTAs
#define EPS_COS  1e-8f
#define EPS_NORM 1e-12f

// Scratch (every slot written every launch)
__device__ float g_dot[NCH_ * B_ * N_];   // [chunk][b][n]
__device__ float g_nsq[NCH_ * B_ * N_];   // [chunk][b][n]
__device__ float g_qsq[NCH_ * B_];        // [chunk][b]
__device__ float g_loss[B_];
__device__ int   g_ticket = 0;            // reset by finalizeB for next replay

// ---------------------------------------------------------------------------
// Kernel 1 (persistent): ticket-scheduled tiles (chunk, b, ph).
// 224 threads = 7 warps, all streaming. Each thread owns one image column.
// ---------------------------------------------------------------------------
__global__ __launch_bounds__(224)
void accum_kernel(const float* __restrict__ qf,
                  const float* __restrict__ rf,
                  const int*   __restrict__ click) {
    __shared__ float smq[CC_ * P_ * P_];   // 784 floats
    __shared__ float sred[2 * 224];
    __shared__ int   s_tile;

    const int tid = threadIdx.x;           // 0..223

    for (;;) {
        __syncthreads();                   // protect s_tile/smq from prev iter
        if (tid == 0) s_tile = atomicAdd(&g_ticket, 1);
        __syncthreads();
        const int t = s_tile;
        if (t >= NTILE_) break;

        // decode: t = ((chunk*B_) + b)*NH_ + ph   (all powers of two)
        const int chunk = t >> 8;
        const int b     = (t >> 4) & 15;
        const int ph    = t & 15;
        const int c0    = chunk * CC_;

        const int qx = click[2 * b + 0];
        const int qy = click[2 * b + 1];
        const int qh = qy / P_;
        const int qw = qx / P_;

        // Stage query patch tile (CC_ x 14 x 14)
        const float* qbase = qf + ((size_t)(b * C_ + c0) * H_ + qh * P_) * W_ + qw * P_;
        for (int idx = tid; idx < CC_ * P_ * P_; idx += 224) {
            int cc = idx / (P_ * P_);
            int r  = idx - cc * (P_ * P_);
            int i  = r / P_;
            int j  = r - i * P_;
            smq[idx] = qbase[(cc * H_ + i) * W_ + j];
        }
        __syncthreads();

        // Stream ref rows: one column per thread, 128B/warp coalesced
        {
            const int w  = tid;
            const int pw = w / P_;
            const int j  = w - pw * P_;
            const float* tbase = rf + ((size_t)(b * C_ + c0) * H_ + ph * P_) * W_ + w;
            float dot = 0.f, nsq = 0.f;
#pragma unroll
            for (int cc = 0; cc < CC_; ++cc) {
                const float* tp = tbase + cc * (H_ * W_);
                const float* qp = smq + cc * (P_ * P_) + j;
#pragma unroll
                for (int i = 0; i < P_; ++i) {
                    float tv = __ldcs(tp + i * W_);   // streaming, evict-first
                    float qv = qp[i * P_];
                    dot = fmaf(tv, qv, dot);
                    nsq = fmaf(tv, tv, nsq);
                }
            }
            sred[w]       = dot;
            sred[224 + w] = nsq;
        }
        __syncthreads();

        // Reduce 14 columns -> one patch; disjoint slots, no atomics
        if (tid < NW_) {
            float d = 0.f, s = 0.f;
#pragma unroll
            for (int k = 0; k < P_; ++k) {
                d += sred[tid * P_ + k];
                s += sred[224 + tid * P_ + k];
            }
            const int n = ph * NW_ + tid;
            g_dot[(chunk * B_ + b) * N_ + n] = d;
            g_nsq[(chunk * B_ + b) * N_ + n] = s;
        }

        // ph==0 tiles also compute partial ||q||^2 (warp shuffle reduce)
        if (ph == 0) {
            float acc = 0.f;
            for (int idx = tid; idx < CC_ * P_ * P_; idx += 224) {
                float v = smq[idx];
                acc = fmaf(v, v, acc);
            }
#pragma unroll
            for (int o = 16; o > 0; o >>= 1)
                acc += __shfl_down_sync(0xffffffffu, acc, o);
            __syncthreads();               // sred readers above are done
            if ((tid & 31) == 0) sred[tid >> 5] = acc;
            __syncthreads();
            if (tid == 0) {
                float s = 0.f;
#pragma unroll
                for (int k = 0; k < 7; ++k) s += sred[k];
                g_qsq[chunk * B_ + b] = s;
            }
        }
    }
}

// ---------------------------------------------------------------------------
// Kernel 2: per-batch cosine-sim -> normalize -> log-softmax -> loss_b
// ---------------------------------------------------------------------------
__global__ __launch_bounds__(256)
void finalizeA_kernel(const float* __restrict__ logit_scale,
                      const int*   __restrict__ gt) {
    const int b   = blockIdx.x;
    const int tid = threadIdx.x;
    __shared__ float sh[256];

    // ||q||^2 = sum of chunk partials
    sh[tid] = (tid < NCH_) ? g_qsq[tid * B_ + b] : 0.f;
    __syncthreads();
    for (int s = 128; s > 0; s >>= 1) {
        if (tid < s) sh[tid] += sh[tid + s];
        __syncthreads();
    }
    const float Qc = fmaxf(sqrtf(sh[0]), EPS_COS);
    __syncthreads();

    // Per-patch (n == tid) sums across chunks
    const int n = tid;
    float dot = 0.f, tsq = 0.f;
#pragma unroll 8
    for (int ch = 0; ch < NCH_; ++ch) {
        dot += g_dot[(ch * B_ + b) * N_ + n];
        tsq += g_nsq[(ch * B_ + b) * N_ + n];
    }
    float s_n = dot / (fmaxf(sqrtf(tsq), EPS_COS) * Qc);

    // F.normalize over the 256-wide sim vector
    sh[tid] = s_n * s_n;
    __syncthreads();
    for (int s = 128; s > 0; s >>= 1) {
        if (tid < s) sh[tid] += sh[tid + s];
        __syncthreads();
    }
    const float r = fmaxf(sqrtf(sh[0]), EPS_NORM);
    __syncthreads();

    const float l = logit_scale[0] * (s_n / r);

    // log-softmax: max
    sh[tid] = l;
    __syncthreads();
    for (int s = 128; s > 0; s >>= 1) {
        if (tid < s) sh[tid] = fmaxf(sh[tid], sh[tid + s]);
        __syncthreads();
    }
    const float m = sh[0];
    __syncthreads();

    // sum exp
    sh[tid] = __expf(l - m);
    __syncthreads();
    for (int s = 128; s > 0; s >>= 1) {
        if (tid < s) sh[tid] += sh[tid + s];
        __syncthreads();
    }
    const float lse = m + logf(sh[0]);

    const int gx = gt[2 * b + 0];
    const int gy = gt[2 * b + 1];
    const int label = (gy / P_) * NW_ + (gx / P_);
    if (n == label) g_loss[b] = lse - l;   // -logp[label]
}

// ---------------------------------------------------------------------------
// Kernel 3: mean over batches + reset ticket for next graph replay
// ---------------------------------------------------------------------------
__global__ void finalizeB_kernel(float* __restrict__ out) {
    if (threadIdx.x == 0) {
        float acc = 0.f;
        for (int b = 0; b < B_; ++b) acc += g_loss[b];
        out[0] = acc / (float)B_;
        g_ticket = 0;                      // reset scheduler for next replay
    }
}

// ---------------------------------------------------------------------------
extern "C" void kernel_launch(void* const* d_in, const int* in_sizes, int n_in,
                              void* d_out, int out_size) {
    const float* qf    = (const float*)d_in[0];   // query_feature [16,256,224,224]
    const float* rf    = (const float*)d_in[1];   // ref_feature   [16,256,224,224]
    const float* scale = (const float*)d_in[2];   // logit_scale scalar
    const int*   click = (const int*)  d_in[3];   // click_points [16,2] int32
    const int*   gt    = (const int*)  d_in[4];   // gt_points    [16,2] int32
    // d_in[5] = patch_size (14), fixed -> hardcoded

    accum_kernel<<<NCTA_, 224>>>(qf, rf, click);
    finalizeA_kernel<<<B_, 256>>>(scale, gt);
    finalizeB_kernel<<<1, 32>>>((float*)d_out);
}